// round 9
// baseline (speedup 1.0000x reference)
#include <cuda_runtime.h>
#include <cuda_bf16.h>
#include <cuda_fp16.h>
#include <math.h>
#include <stdint.h>

// Problem constants
#define B_SZ 512
#define T_SZ 64
#define I_SZ 64
#define H_SZ 128
#define G_SZ 384   // 3*H

// ---------------- device scratch (no allocations allowed) ----------------
__device__ uint32_t g_P [I_SZ * 24576];             // per-feature W_hh, fp16 B-fragment layout
__device__ float g_hs[B_SZ * I_SZ * H_SZ];          // GRU final hidden
__device__ float g_A [B_SZ * I_SZ * H_SZ];          // xT
__device__ float g_Wt[7 * H_SZ * H_SZ];             // transposed tail weights

__device__ __forceinline__ void mma_f16(float* d, const uint32_t* a, uint32_t b0, uint32_t b1) {
    asm volatile(
        "mma.sync.aligned.m16n8k16.row.col.f32.f16.f16.f32 "
        "{%0,%1,%2,%3}, {%4,%5,%6,%7}, {%8,%9}, {%0,%1,%2,%3};"
        : "+f"(d[0]), "+f"(d[1]), "+f"(d[2]), "+f"(d[3])
        : "r"(a[0]), "r"(a[1]), "r"(a[2]), "r"(a[3]), "r"(b0), "r"(b1));
}

__device__ __forceinline__ __half2 tanh2(__half2 v) {
    uint32_t o, in = *reinterpret_cast<uint32_t*>(&v);
    asm("tanh.approx.f16x2 %0, %1;" : "=r"(o) : "r"(in));
    return *reinterpret_cast<__half2*>(&o);
}

// ---------------- pack W_hh: fp16 B-fragment layout for 16-warp/8-j-slice config ----------------
// P[i][ (((wid*3+g3)*8+kt)*64 + lane*2 + reg ] = half2( W[g3*128+j][k0], W[...][k0+1] )
// j = 8*wid + (lane>>2) ; k0 = 16kt + 8reg + 2(lane&3) ; r/z rows pre-scaled by 0.5
__global__ void pack_whh_kernel(const float* __restrict__ W_hh, uint32_t* __restrict__ P)
{
    int idx = blockIdx.x * blockDim.x + threadIdx.x;
    if (idx >= I_SZ * 24576) return;
    int i = idx / 24576;
    int r = idx % 24576;
    int wid = r / 1536; r %= 1536;
    int g3  = r / 512;  r %= 512;
    int kt  = r / 64;   r %= 64;
    int lane = r >> 1;
    int reg  = r & 1;
    int k0 = 16 * kt + 8 * reg + 2 * (lane & 3);
    int j  = 8 * wid + (lane >> 2);
    float scale = (g3 < 2) ? 0.5f : 1.0f;
    const float* src = W_hh + ((size_t)i * G_SZ + g3 * 128 + j) * H_SZ + k0;
    __half2 h2 = __floats2half2_rn(scale * src[0], scale * src[1]);
    P[idx] = *reinterpret_cast<uint32_t*>(&h2);
}

// ---------------- transpose x: xT[t][i][b] = x[b][t][i] ----------------
__global__ void xt_kernel(const float* __restrict__ x, float* __restrict__ xT)
{
    int idx = blockIdx.x * blockDim.x + threadIdx.x;
    if (idx >= B_SZ * T_SZ * I_SZ) return;
    int b = idx & 511;
    int r = idx >> 9;
    int i = r & 63;
    int t = r >> 6;
    xT[idx] = x[((size_t)b * T_SZ + t) * I_SZ + i];
}

// ---------------- transpose the 7 [H,H] weight matrices ----------------
__global__ void transpose7_kernel(const float* __restrict__ fp, const float* __restrict__ g1,
                                  const float* __restrict__ g2, const float* __restrict__ wk,
                                  const float* __restrict__ wv, const float* __restrict__ wq,
                                  const float* __restrict__ o0, float* __restrict__ out)
{
    int idx = blockIdx.x * blockDim.x + threadIdx.x;
    if (idx >= 7 * H_SZ * H_SZ) return;
    int w = idx >> 14;
    int r = idx & 16383;
    int k = r >> 7, n = r & 127;
    const float* src = (w == 0) ? fp : (w == 1) ? g1 : (w == 2) ? g2 :
                       (w == 3) ? wk : (w == 4) ? wv : (w == 5) ? wq : o0;
    out[idx] = src[n * 128 + k];
}

// ---------------- GRU scan: B resident in registers, 512 threads ----------------
// grid = (16 batch-blocks of 32, 64 features), 512 threads (16 warps)
// warp wid owns j in [8wid, 8wid+8) x 3 gates; M=32 (2 m-tiles); K=128 (8 kt)
// B frags (48 u32) loaded ONCE. SMEM = double-buffered A tile only.
__global__ __launch_bounds__(512, 1) void gru_kernel(
    const float* __restrict__ xT,     // [T][I][B]
    const uint32_t* __restrict__ P,
    const float* __restrict__ W_ih,   // [I][3H]
    const float* __restrict__ b_ih,
    const float* __restrict__ b_hh,
    float* __restrict__ hs_out)       // [B][I][H]
{
    __shared__ uint4 s_A[2][16 * 32];     // [buf][(kt*2+mt)*32 + lane]

    const int i   = blockIdx.y;
    const int b0  = blockIdx.x * 32;
    const int tid = threadIdx.x;
    const int wid  = tid >> 5;
    const int lane = tid & 31;
    const int g    = lane >> 2;
    const int t4   = lane & 3;

    // ---- load B fragments into registers (once) ----
    uint32_t Breg[3][8][2];
    {
        const uint2* src = (const uint2*)(P + (size_t)i * 24576) + (wid * 24) * 32 + lane;
#pragma unroll
        for (int g3 = 0; g3 < 3; g3++)
#pragma unroll
            for (int kt = 0; kt < 8; kt++) {
                uint2 v = src[(g3 * 8 + kt) * 32];
                Breg[g3][kt][0] = v.x;
                Breg[g3][kt][1] = v.y;
            }
    }

    // ---- per-thread gate constants for 2 j-values (j = 8wid + 2t4 + dj) ----
    const int jb = 8 * wid + 2 * t4;
    const int base = i * G_SZ + jb;
    float wr[2], wz[2], wn[2], bin[2], ccr[2], ccz[2], bhn[2];
#pragma unroll
    for (int dj = 0; dj < 2; dj++) {
        wr[dj]  = 0.5f * __ldg(&W_ih[base + dj]);
        wz[dj]  = 0.5f * __ldg(&W_ih[base + 128 + dj]);
        wn[dj]  = __ldg(&W_ih[base + 256 + dj]);
        ccr[dj] = 0.5f * (__ldg(&b_ih[base + dj])       + __ldg(&b_hh[base + dj]));
        ccz[dj] = 0.5f * (__ldg(&b_ih[base + 128 + dj]) + __ldg(&b_hh[base + 128 + dj]));
        bin[dj] = __ldg(&b_ih[base + 256 + dj]);
        bhn[dj] = __ldg(&b_hh[base + 256 + dj]);
    }

    // h state: hq[mt][hi] = half2 over dj; rows m = 16mt + g + 8hi
    __half2 hq[2][2];
    const __half2 hhalf = __float2half2_rn(0.5f);
    hq[0][0] = hq[0][1] = hq[1][0] = hq[1][1] = __float2half2_rn(0.0f);

    const int kt_self = wid >> 1;            // A-tile cell this warp feeds
    const int half_off = wid & 1;            // a0/a1 vs a2/a3
    const float* xrow = xT + (size_t)i * B_SZ + b0;

    for (int t = 0; t < T_SZ; t++) {
        uint4* sA = s_A[t & 1];

        // ---- write h_t fragments (uint2 = rows g, g+8 for this lane's k-pair) ----
        if (t > 0) {
#pragma unroll
            for (int mt = 0; mt < 2; mt++) {
                uint2* cell = (uint2*)&sA[(kt_self * 2 + mt) * 32 + lane];
                cell[half_off] = make_uint2(*reinterpret_cast<uint32_t*>(&hq[mt][0]),
                                            *reinterpret_cast<uint32_t*>(&hq[mt][1]));
            }
        }
        __syncthreads();

        // ---- D init with folded gate constants ----
        float D[2][3][4];
#pragma unroll
        for (int mt = 0; mt < 2; mt++) {
#pragma unroll
            for (int c = 0; c < 4; c++) {
                D[mt][0][c] = ccr[c & 1];
                D[mt][1][c] = ccz[c & 1];
                D[mt][2][c] = bhn[c & 1];
            }
        }

        // ---- GEMM: only A from SMEM, B from registers ----
        if (t > 0) {
#pragma unroll
            for (int kt = 0; kt < 8; kt++) {
                uint4 a0 = sA[(kt * 2 + 0) * 32 + lane];
                uint4 a1 = sA[(kt * 2 + 1) * 32 + lane];
                uint32_t af0[4] = {a0.x, a0.y, a0.z, a0.w};
                uint32_t af1[4] = {a1.x, a1.y, a1.z, a1.w};
#pragma unroll
                for (int g3 = 0; g3 < 3; g3++) {
                    mma_f16(D[0][g3], af0, Breg[g3][kt][0], Breg[g3][kt][1]);
                    mma_f16(D[1][g3], af1, Breg[g3][kt][0], Breg[g3][kt][1]);
                }
            }
        }

        // ---- epilogue: 8 elements/thread, f16x2 gates ----
#pragma unroll
        for (int mt = 0; mt < 2; mt++) {
#pragma unroll
            for (int hi = 0; hi < 2; hi++) {
                const float xt = __ldg(xrow + 16 * mt + g + 8 * hi);
                const int c0 = 2 * hi, c1 = 2 * hi + 1;
                const float ur0 = fmaf(xt, wr[0], D[mt][0][c0]);
                const float ur1 = fmaf(xt, wr[1], D[mt][0][c1]);
                const __half2 r2 = __hfma2(tanh2(__floats2half2_rn(ur0, ur1)), hhalf, hhalf);
                const float uz0 = fmaf(xt, wz[0], D[mt][1][c0]);
                const float uz1 = fmaf(xt, wz[1], D[mt][1][c1]);
                const __half2 z2 = __hfma2(tanh2(__floats2half2_rn(uz0, uz1)), hhalf, hhalf);
                const float in0 = fmaf(xt, wn[0], bin[0]);
                const float in1 = fmaf(xt, wn[1], bin[1]);
                const __half2 inn2 = __floats2half2_rn(in0, in1);
                const __half2 hn2  = __floats2half2_rn(D[mt][2][c0], D[mt][2][c1]);
                const __half2 th2  = tanh2(__hfma2(r2, hn2, inn2));
                const __half2 hold = hq[mt][hi];
                hq[mt][hi] = __hfma2(z2, __hsub2(hold, th2), th2);
            }
        }
        xrow += I_SZ * B_SZ;
    }

    // ---- write final hidden state: hs[b][i][jb..jb+1] ----
#pragma unroll
    for (int mt = 0; mt < 2; mt++)
#pragma unroll
        for (int hi = 0; hi < 2; hi++) {
            const int b = b0 + 16 * mt + g + 8 * hi;
            float2 f = __half22float2(hq[mt][hi]);
            *(float2*)(hs_out + ((size_t)b * I_SZ + i) * H_SZ + jb) = f;
        }
}

// ---------------- fused tail helpers (smem-resident per-batch pipeline) ----------------
__device__ __forceinline__ void lin_smem(const float* __restrict__ Xin, const float* __restrict__ Wt,
                                         const float* __restrict__ bias, float* __restrict__ Yout,
                                         float* __restrict__ gout, int relu, int w, int l)
{
    const int r0 = w * 8;
    float acc[8][4];
#pragma unroll
    for (int rr = 0; rr < 8; rr++)
#pragma unroll
        for (int c = 0; c < 4; c++) acc[rr][c] = 0.f;
#pragma unroll 4
    for (int k = 0; k < 128; k++) {
        float wv[4];
#pragma unroll
        for (int c = 0; c < 4; c++) wv[c] = __ldg(&Wt[k * 128 + l + 32 * c]);
#pragma unroll
        for (int rr = 0; rr < 8; rr++) {
            const float xv = Xin[(r0 + rr) * 128 + k];
#pragma unroll
            for (int c = 0; c < 4; c++) acc[rr][c] = fmaf(xv, wv[c], acc[rr][c]);
        }
    }
#pragma unroll
    for (int rr = 0; rr < 8; rr++)
#pragma unroll
        for (int c = 0; c < 4; c++) {
            const int n = l + 32 * c;
            float v = acc[rr][c] + __ldg(&bias[n]);
            if (relu) v = fmaxf(v, 0.f);
            Yout[(r0 + rr) * 128 + n] = v;
            if (gout) gout[(size_t)(r0 + rr) * 128 + n] = v;
        }
}

__device__ __forceinline__ void adj_smem(const float* __restrict__ Xin, const float* __restrict__ adj,
                                         float* __restrict__ Yout, int w, int l)
{
    const int i0 = w * 8;
    float acc[8][4];
#pragma unroll
    for (int ii = 0; ii < 8; ii++)
#pragma unroll
        for (int c = 0; c < 4; c++) acc[ii][c] = 0.f;
#pragma unroll 4
    for (int j = 0; j < 64; j++) {
        float hv[4];
#pragma unroll
        for (int c = 0; c < 4; c++) hv[c] = Xin[j * 128 + l + 32 * c];
#pragma unroll
        for (int ii = 0; ii < 8; ii++) {
            const float a = __ldg(&adj[(i0 + ii) * 64 + j]);
#pragma unroll
            for (int c = 0; c < 4; c++) acc[ii][c] = fmaf(a, hv[c], acc[ii][c]);
        }
    }
#pragma unroll
    for (int ii = 0; ii < 8; ii++)
#pragma unroll
        for (int c = 0; c < 4; c++)
            Yout[(i0 + ii) * 128 + l + 32 * c] = acc[ii][c];
}

// one block per batch: hs -> ht(out) -> adj -> g1 -> adj -> g2 -> attention -> out
#define TAIL_SMEM (16384 * 4 + 4 * (128 * 4 + 64 + 2) + 256)

__global__ __launch_bounds__(256) void tail_kernel(
    const float* __restrict__ hs, const float* __restrict__ adj,
    const float* __restrict__ fpT, const float* __restrict__ fp_b,
    const float* __restrict__ g1T, const float* __restrict__ g1_b,
    const float* __restrict__ g2T, const float* __restrict__ g2_b,
    const float* __restrict__ wqT, const float* __restrict__ wq_b,
    const float* __restrict__ wk_w, const float* __restrict__ wk_b,
    const float* __restrict__ wvT, const float* __restrict__ wv_b,
    const float* __restrict__ o0T, const float* __restrict__ o0_b,
    float* __restrict__ ht_out, float* __restrict__ out)
{
    extern __shared__ float sm[];
    float* Xs = sm;                  // [64][128]
    float* Zs = sm + 8192;           // [64][128]
    float* q  = sm + 16384;
    float* u  = q + 128;
    float* s  = u + 128;
    float* wc = s + 128;
    float* ev = wc + 128;
    float* red = ev + 64;

    const int b = blockIdx.x;
    const int tid = threadIdx.x, w = tid >> 5, l = tid & 31;

    for (int idx = tid; idx < 8192; idx += 256)
        Xs[idx] = hs[(size_t)b * 8192 + idx];
    __syncthreads();

    lin_smem(Xs, fpT, fp_b, Zs, ht_out + (size_t)b * 8192, 0, w, l);
    __syncthreads();
    adj_smem(Zs, adj, Xs, w, l);
    __syncthreads();
    lin_smem(Xs, g1T, g1_b, Zs, nullptr, 1, w, l);
    __syncthreads();
    adj_smem(Zs, adj, Xs, w, l);
    __syncthreads();
    lin_smem(Xs, g2T, g2_b, Zs, nullptr, 1, w, l);   // Zs = ctx
    __syncthreads();

    // ---- attention on ctx (Zs) ----
    if (tid < 128) {
        float acc = __ldg(&wq_b[tid]);
        for (int k = 0; k < 128; k++)
            acc = fmaf(Zs[63 * 128 + k], __ldg(&wqT[k * 128 + tid]), acc);
        q[tid] = acc;
    }
    __syncthreads();
    if (tid < 128) {
        float acc = 0.f;
        for (int n = 0; n < 128; n++)
            acc = fmaf(q[n], __ldg(&wk_w[n * 128 + tid]), acc);
        u[tid] = acc;
    }
    if (tid == 128) {
        float c = 0.f;
        for (int n = 0; n < 128; n++) c = fmaf(q[n], __ldg(&wk_b[n]), c);
        red[0] = c;
    }
    __syncthreads();
    if (tid < 64) {
        float e = red[0];
        for (int k = 0; k < 128; k++) e = fmaf(Zs[tid * 128 + k], u[k], e);
        ev[tid] = e;
    }
    __syncthreads();
    if (tid == 0) {
        float mx = -1e30f;
        for (int ii = 0; ii < 64; ii++) mx = fmaxf(mx, ev[ii]);
        float smm = 0.f;
        for (int ii = 0; ii < 64; ii++) smm += __expf(ev[ii] - mx);
        red[0] = mx; red[1] = 1.0f / smm;
    }
    __syncthreads();
    if (tid < 64) ev[tid] = __expf(ev[tid] - red[0]) * red[1];
    __syncthreads();
    if (tid < 128) {
        float acc = 0.f;
        for (int ii = 0; ii < 64; ii++) acc = fmaf(ev[ii], Zs[ii * 128 + tid], acc);
        s[tid] = acc;
    }
    __syncthreads();
    if (tid < 128) {
        float acc = __ldg(&wv_b[tid]);
        for (int k = 0; k < 128; k++) acc = fmaf(s[k], __ldg(&wvT[k * 128 + tid]), acc);
        wc[tid] = acc;
    }
    __syncthreads();
    if (tid < 128) {
        float acc = __ldg(&o0_b[tid]);
        for (int m = 0; m < 128; m++) acc = fmaf(wc[m], __ldg(&o0T[m * 128 + tid]), acc);
        out[(size_t)b * 128 + tid] = fmaxf(acc, 0.f);
    }
}

// ---------------- launch ----------------
extern "C" void kernel_launch(void* const* d_in, const int* in_sizes, int n_in,
                              void* d_out, int out_size)
{
    const float* x     = (const float*)d_in[0];
    const float* W_ih  = (const float*)d_in[1];
    const float* W_hh  = (const float*)d_in[2];
    const float* b_ih  = (const float*)d_in[3];
    const float* b_hh  = (const float*)d_in[4];
    const float* fp_w  = (const float*)d_in[5];
    const float* fp_b  = (const float*)d_in[6];
    const float* g1_w  = (const float*)d_in[7];
    const float* g1_b  = (const float*)d_in[8];
    const float* g2_w  = (const float*)d_in[9];
    const float* g2_b  = (const float*)d_in[10];
    const float* wq_w  = (const float*)d_in[11];
    const float* wq_b  = (const float*)d_in[12];
    const float* wk_w  = (const float*)d_in[13];
    const float* wk_b  = (const float*)d_in[14];
    const float* wv_w  = (const float*)d_in[15];
    const float* wv_b  = (const float*)d_in[16];
    const float* o0_w  = (const float*)d_in[17];
    const float* o0_b  = (const float*)d_in[18];
    const float* adj   = (const float*)d_in[19];

    float* out = (float*)d_out;
    float* ht_out = out + B_SZ * H_SZ;

    uint32_t* P;
    float *hs, *A, *Wt;
    cudaGetSymbolAddress((void**)&P,  g_P);
    cudaGetSymbolAddress((void**)&hs, g_hs);
    cudaGetSymbolAddress((void**)&A,  g_A);
    cudaGetSymbolAddress((void**)&Wt, g_Wt);

    cudaFuncSetAttribute(tail_kernel, cudaFuncAttributeMaxDynamicSharedMemorySize, TAIL_SMEM);

    // prep
    pack_whh_kernel<<<(I_SZ * 24576 + 255) / 256, 256>>>(W_hh, P);
    transpose7_kernel<<<(7 * H_SZ * H_SZ + 255) / 256, 256>>>(fp_w, g1_w, g2_w, wk_w, wv_w, wq_w, o0_w, Wt);
    xt_kernel<<<(B_SZ * T_SZ * I_SZ + 255) / 256, 256>>>(x, A);

    const float* fpT = Wt + 0 * 16384;
    const float* g1T = Wt + 1 * 16384;
    const float* g2T = Wt + 2 * 16384;
    const float* wvT = Wt + 4 * 16384;
    const float* wqT = Wt + 5 * 16384;
    const float* o0T = Wt + 6 * 16384;

    // 1) GRU scan -> hs (B in registers)
    gru_kernel<<<dim3(16, 64), 512>>>(A, P, W_ih, b_ih, b_hh, hs);

    // 2) fused tail
    tail_kernel<<<B_SZ, 256, TAIL_SMEM>>>(hs, adj,
                                          fpT, fp_b, g1T, g1_b, g2T, g2_b,
                                          wqT, wq_b, wk_w, wk_b, wvT, wv_b,
                                          o0T, o0_b, ht_out, out);
}